// round 2
// baseline (speedup 1.0000x reference)
#include <cuda_runtime.h>
#include <math.h>

#define BSZ   1024
#define TH2   1024
#define KK    128
#define ADIM  64
#define LL    6
#define TT    60
#define NEGINF (-1e38f)

// ---------------- scratch (device globals; no cudaMalloc allowed) ----------
__device__ float g_pi[BSZ * KK];            // 512 KB
__device__ float g_h[BSZ * 8192];           // 32 MB
__device__ float g_cond[(size_t)BSZ * 16384]; // 64 MB
__device__ float g_ts[KK * KK];             // 64 KB

// ---------------- pi = log_softmax(uniqenc @ W_init + b_init) --------------
__global__ void __launch_bounds__(128) pi_kernel(
    const float* __restrict__ U, const float* __restrict__ W,
    const float* __restrict__ bias, float* __restrict__ pi) {
    __shared__ float u[TH2];
    __shared__ float red[4];
    int b = blockIdx.x, tid = threadIdx.x;
    for (int i = tid; i < TH2; i += 128) u[i] = U[b * TH2 + i];
    __syncthreads();
    float acc = bias[tid];
#pragma unroll 8
    for (int kk = 0; kk < TH2; kk++) acc += u[kk] * W[kk * KK + tid];
    // block max (128 threads = 4 warps)
    float m = acc;
    for (int o = 16; o; o >>= 1) m = fmaxf(m, __shfl_xor_sync(~0u, m, o));
    if ((tid & 31) == 0) red[tid >> 5] = m;
    __syncthreads();
    m = fmaxf(fmaxf(red[0], red[1]), fmaxf(red[2], red[3]));
    __syncthreads();
    float e = __expf(acc - m);
    float s = e;
    for (int o = 16; o; o >>= 1) s += __shfl_xor_sync(~0u, s, o);
    if ((tid & 31) == 0) red[tid >> 5] = s;
    __syncthreads();
    s = red[0] + red[1] + red[2] + red[3];
    pi[b * KK + tid] = acc - m - __logf(s);
}

// ---------------- tscores = A_from @ A_to + diag(NEGINF) -------------------
__global__ void __launch_bounds__(128) tscores_kernel(
    const float* __restrict__ Af, const float* __restrict__ At,
    float* __restrict__ ts) {
    int k = blockIdx.x, j = threadIdx.x;
    float acc = (j == k) ? NEGINF : 0.f;
#pragma unroll
    for (int a = 0; a < ADIM; a++) acc += Af[k * ADIM + a] * At[a * KK + j];
    ts[k * KK + j] = acc;
}

// ---------------- tiled fp32 GEMM: C = act(A@B + bias) ---------------------
// A: MxK row-major, B: KxN row-major, C: MxN row-major. M,N mult of 128, K mult of 16.
#define BM 128
#define BN 128
#define BKD 16
template <bool RELU>
__global__ void __launch_bounds__(256, 2) gemm_bias(
    const float* __restrict__ A, const float* __restrict__ B,
    const float* __restrict__ bias, float* __restrict__ C,
    int M, int N, int Kd) {
    __shared__ float As[BKD][BM];
    __shared__ float Bs[BKD][BN];
    int tid = threadIdx.x;
    int tx = tid & 15, ty = tid >> 4;   // 16x16 thread grid, 8x8 microtile
    int m0 = blockIdx.y * BM, n0 = blockIdx.x * BN;
    const float* Aptr = A + (size_t)m0 * Kd;
    const float* Bptr = B + n0;
    float acc[8][8];
#pragma unroll
    for (int i = 0; i < 8; i++)
#pragma unroll
        for (int j = 0; j < 8; j++) acc[i][j] = 0.f;

    for (int kt = 0; kt < Kd; kt += BKD) {
#pragma unroll
        for (int it = 0; it < 2; it++) {
            int f = tid + it * 256;
            // A tile 128x16 -> transposed into As[k][m]
            int ar = f >> 2, ac = (f & 3) * 4;
            float4 av = *(const float4*)(Aptr + (size_t)ar * Kd + kt + ac);
            As[ac + 0][ar] = av.x; As[ac + 1][ar] = av.y;
            As[ac + 2][ar] = av.z; As[ac + 3][ar] = av.w;
            // B tile 16x128
            int br = f >> 5, bc = (f & 31) * 4;
            float4 bv = *(const float4*)(Bptr + (size_t)(kt + br) * N + bc);
            *(float4*)&Bs[br][bc] = bv;
        }
        __syncthreads();
#pragma unroll
        for (int k = 0; k < BKD; k++) {
            float a[8], bb[8];
#pragma unroll
            for (int i = 0; i < 8; i++) a[i] = As[k][ty * 8 + i];
#pragma unroll
            for (int j = 0; j < 8; j++) bb[j] = Bs[k][tx * 8 + j];
#pragma unroll
            for (int i = 0; i < 8; i++)
#pragma unroll
                for (int j = 0; j < 8; j++) acc[i][j] += a[i] * bb[j];
        }
        __syncthreads();
    }
#pragma unroll
    for (int i = 0; i < 8; i++) {
        int m = m0 + ty * 8 + i;
#pragma unroll
        for (int j = 0; j < 8; j += 4) {
            float4 o;
            float* op = &o.x;
#pragma unroll
            for (int q = 0; q < 4; q++) {
                float v = acc[i][j + q] + bias[n0 + tx * 8 + j + q];
                if (RELU) v = fmaxf(v, 0.f);
                op[q] = v;
            }
            *(float4*)(C + (size_t)m * N + n0 + tx * 8 + j) = o;
        }
    }
}

// ---------------- fused trans-build + HSMM recurrence (1 block / batch) ----
// SMEM layout (floats):
//  T   : 128*129  (padded transition probs exp(log_softmax))
//  cf  : 128*64   cond_from
//  ct  : 128*65   cond_to (padded)
//  buf : 6*128    circular alpha* buffer
//  av  : 128, ap : 128, ps : 256, red : 8
#define SM_T    0
#define SM_CF   (SM_T + 128 * 129)
#define SM_CT   (SM_CF + 128 * 64)
#define SM_BUF  (SM_CT + 128 * 65)
#define SM_AV   (SM_BUF + 6 * 128)
#define SM_AP   (SM_AV + 128)
#define SM_PS   (SM_AP + 128)
#define SM_RED  (SM_PS + 256)
#define SM_TOTF (SM_RED + 8)
#define RECUR_SMEM (SM_TOTF * 4)

__global__ void __launch_bounds__(256, 1) recur_kernel(
    const float* __restrict__ pi, const float* __restrict__ cond,
    const float* __restrict__ ts, const float* __restrict__ obs,
    float* __restrict__ out) {
    extern __shared__ float sm[];
    float* T   = sm + SM_T;
    float* cf  = sm + SM_CF;
    float* ct  = sm + SM_CT;
    float* buf = sm + SM_BUF;
    float* av  = sm + SM_AV;
    float* ap  = sm + SM_AP;
    float* ps  = sm + SM_PS;
    float* red = sm + SM_RED;
    int tid = threadIdx.x, b = blockIdx.x;

    // Phase A: load cond_from / cond_to (cond row: [k][0:64]=from, [64:128]=to)
    const float* crow = cond + (size_t)b * (KK * 2 * ADIM);
    for (int i = tid; i < 128 * 64; i += 256) {
        int k = i >> 6, a = i & 63;
        float2 v;
        v.x = crow[k * 128 + a];
        v.y = crow[k * 128 + 64 + a];
        cf[k * 64 + a] = v.x;
        ct[k * 65 + a] = v.y;
    }
    __syncthreads();

    // Phase B: logits[k][j] = ts[k][j] + dot(cf[k], ct[j])  (2k x 4j microtiles)
    for (int mi = tid; mi < 2048; mi += 256) {
        int km = mi >> 5, jm = mi & 31;
        int k0 = km * 2;
        const float* f0 = cf + k0 * 64;
        const float* f1 = f0 + 64;
        float acc[2][4];
#pragma unroll
        for (int r = 0; r < 2; r++)
#pragma unroll
            for (int q = 0; q < 4; q++)
                acc[r][q] = ts[(k0 + r) * KK + jm + 32 * q];
#pragma unroll 16
        for (int a = 0; a < 64; a++) {
            float fa0 = f0[a], fa1 = f1[a];
#pragma unroll
            for (int q = 0; q < 4; q++) {
                float tv = ct[(jm + 32 * q) * 65 + a];
                acc[0][q] += fa0 * tv;
                acc[1][q] += fa1 * tv;
            }
        }
#pragma unroll
        for (int r = 0; r < 2; r++)
#pragma unroll
            for (int q = 0; q < 4; q++)
                T[(k0 + r) * 129 + jm + 32 * q] = acc[r][q];
    }
    __syncthreads();

    // Phase C: per-row softmax over j, store probabilities exp(log_softmax)
    {
        int w = tid >> 5, lane = tid & 31;
        for (int r = 0; r < 16; r++) {
            int k = w * 16 + r;
            float v0 = T[k * 129 + lane];
            float v1 = T[k * 129 + lane + 32];
            float v2 = T[k * 129 + lane + 64];
            float v3 = T[k * 129 + lane + 96];
            float m = fmaxf(fmaxf(v0, v1), fmaxf(v2, v3));
            for (int o = 16; o; o >>= 1) m = fmaxf(m, __shfl_xor_sync(~0u, m, o));
            float e0 = __expf(v0 - m), e1 = __expf(v1 - m);
            float e2 = __expf(v2 - m), e3 = __expf(v3 - m);
            float s = e0 + e1 + e2 + e3;
            for (int o = 16; o; o >>= 1) s += __shfl_xor_sync(~0u, s, o);
            float inv = 1.f / s;
            T[k * 129 + lane]      = e0 * inv;
            T[k * 129 + lane + 32] = e1 * inv;
            T[k * 129 + lane + 64] = e2 * inv;
            T[k * 129 + lane + 96] = e3 * inv;
        }
    }

    // Phase D: init circular buffer  buf[0]=pi, rest NEGINF
    for (int i = tid; i < LL * KK; i += 256) buf[i] = NEGINF;
    __syncthreads();
    if (tid < 128) buf[tid] = pi[b * KK + tid];
    __syncthreads();

    int head = 0;
    const float len_lp = -1.7917594692280550f; // -log(6)
    for (int t = 0; t < TT; t++) {
        if (tid < 128) {
            int j = tid;
            float s[LL];
            float m = -3.4e38f;
#pragma unroll
            for (int l = 0; l < LL; l++) {
                int tp = t - l;
                float o = (tp >= 0)
                    ? obs[(((size_t)l * TT + tp) * BSZ + b) * KK + j]
                    : NEGINF;
                int row = head + l; if (row >= LL) row -= LL;
                float v = buf[row * KK + j] + o;
                s[l] = v;
                m = fmaxf(m, v);
            }
            float se = 0.f;
#pragma unroll
            for (int l = 0; l < LL; l++) se += __expf(s[l] - m);
            float al = m + __logf(se) + len_lp;
            av[j] = al;
            float wm = al;
            for (int o = 16; o; o >>= 1) wm = fmaxf(wm, __shfl_xor_sync(~0u, wm, o));
            if ((tid & 31) == 0) red[tid >> 5] = wm;
        }
        __syncthreads();
        float am = fmaxf(fmaxf(red[0], red[1]), fmaxf(red[2], red[3]));
        if (tid < 128) ap[tid] = __expf(av[tid] - am);
        __syncthreads();
        // astar via probability-space matvec: two half-K partials per j
        {
            int j = tid & 127, hk = (tid >> 7) << 6;
            float acc = 0.f;
            const float* Tp = T + hk * 129 + j;
            const float* pp = ap + hk;
#pragma unroll 8
            for (int k = 0; k < 64; k++) acc += pp[k] * Tp[k * 129];
            ps[tid] = acc;
        }
        __syncthreads();
        int nh = (head == 0) ? (LL - 1) : (head - 1);
        if (tid < 128) {
            float ssum = ps[tid] + ps[128 + tid];
            float astar = am + __logf(ssum);
            if (!(astar > NEGINF)) astar = NEGINF;  // clamp -inf (underflow)
            buf[nh * KK + tid] = astar;
        }
        head = nh;
        __syncthreads();
    }
    // Output: logsumexp over j of alpha at t=59 (ap/red still hold t=59 state)
    if (tid < 128) {
        float v = ap[tid];
        for (int o = 16; o; o >>= 1) v += __shfl_xor_sync(~0u, v, o);
        if ((tid & 31) == 0) red[4 + (tid >> 5)] = v;
    }
    __syncthreads();
    if (tid == 0) {
        float s = red[4] + red[5] + red[6] + red[7];
        float am = fmaxf(fmaxf(red[0], red[1]), fmaxf(red[2], red[3]));
        out[b] = am + __logf(s);
    }
}

// ---------------- launch ---------------------------------------------------
extern "C" void kernel_launch(void* const* d_in, const int* in_sizes, int n_in,
                              void* d_out, int out_size) {
    const float* uniqenc = (const float*)d_in[0];
    const float* obs_lps = (const float*)d_in[1];
    const float* W_init  = (const float*)d_in[2];
    const float* b_init  = (const float*)d_in[3];
    const float* A_from  = (const float*)d_in[4];
    const float* A_to    = (const float*)d_in[5];
    const float* W_c1    = (const float*)d_in[6];
    const float* b_c1    = (const float*)d_in[7];
    const float* W_c2    = (const float*)d_in[8];
    const float* b_c2    = (const float*)d_in[9];
    float* out = (float*)d_out;

    float *pi_p, *h_p, *cond_p, *ts_p;
    cudaGetSymbolAddress((void**)&pi_p, g_pi);
    cudaGetSymbolAddress((void**)&h_p, g_h);
    cudaGetSymbolAddress((void**)&cond_p, g_cond);
    cudaGetSymbolAddress((void**)&ts_p, g_ts);
    cudaFuncSetAttribute(recur_kernel,
                         cudaFuncAttributeMaxDynamicSharedMemorySize, RECUR_SMEM);

    pi_kernel<<<BSZ, 128>>>(uniqenc, W_init, b_init, pi_p);
    tscores_kernel<<<KK, 128>>>(A_from, A_to, ts_p);
    gemm_bias<true><<<dim3(8192 / BN, BSZ / BM), 256>>>(
        uniqenc, W_c1, b_c1, h_p, BSZ, 8192, TH2);
    gemm_bias<false><<<dim3(16384 / BN, BSZ / BM), 256>>>(
        h_p, W_c2, b_c2, cond_p, BSZ, 16384, 8192);
    recur_kernel<<<BSZ, 256, RECUR_SMEM>>>(pi_p, cond_p, ts_p, obs_lps, out);
}

// round 12
// speedup vs baseline: 2.9033x; 2.9033x over previous
#include <cuda_runtime.h>
#include <cstdint>
#include <math.h>

#define BSZ   1024
#define TH2   1024
#define KK    128
#define ADIM  64
#define LL    6
#define TT    60
#define NEGINF (-1e38f)

// ---------------- scratch (device globals; no cudaMalloc allowed) ----------
__device__ float g_pi[BSZ * KK];              // 512 KB
__device__ float g_h[BSZ * 8192];             // 32 MB
__device__ float g_cond[(size_t)BSZ * 16384]; // 64 MB
__device__ float g_ts[KK * KK];               // 64 KB

// =================== helpers (family-baseline PTX only) ====================
__device__ __forceinline__ uint32_t smem_u32(const void* p) {
    uint32_t a;
    asm("{ .reg .u64 t; cvta.to.shared.u64 t, %1; cvt.u32.u64 %0, t; }"
        : "=r"(a) : "l"(p));
    return a;
}
#define CP_ASYNC16(dst, src) \
    asm volatile("cp.async.cg.shared.global [%0], [%1], 16;" \
                 :: "r"(dst), "l"(src) : "memory")
#define CP_COMMIT() asm volatile("cp.async.commit_group;" ::: "memory")
#define CP_WAIT1()  asm volatile("cp.async.wait_group 1;" ::: "memory")

// =================== tensor-core GEMM via mma.sync (tf32) ==================
// C[M][N] = act(A[M][Kd] @ B[Kd][N] + bias).  Block 128x128, K-chunk 32,
// 8 warps each 64x32 (4x4 m16n8k8 tiles), 2-stage cp.async double buffer.
// SMEM: As[2][128][36] (pad-> banks 4r+c distinct), Bs[2][32][136] (8k+n distinct)
#define ASTR 36
#define BSTR 136
#define A_ST (128 * ASTR)          // floats per A stage  (4608)
#define B_ST (32 * BSTR)           // floats per B stage  (4352)
#define B_BASE (2 * A_ST)          // 9216
#define GSMEM ((B_BASE + 2 * B_ST) * 4)   // 71680 bytes

template <bool RELU>
__global__ void __launch_bounds__(256, 2) gemm_mma(
    const float* __restrict__ A, const float* __restrict__ B,
    const float* __restrict__ bias, float* __restrict__ C,
    int M, int N, int Kd) {
    extern __shared__ float sm[];
    uint32_t smb = smem_u32(sm);
    int tid = threadIdx.x, lane = tid & 31, wid = tid >> 5;
    int wm = wid & 1, wn = wid >> 1;      // 2 warps in M, 4 in N
    int m0 = blockIdx.x * 128, n0 = blockIdx.y * 128;
    const int NC = Kd >> 5;

    float acc[4][4][4];
#pragma unroll
    for (int mt = 0; mt < 4; mt++)
#pragma unroll
        for (int nt = 0; nt < 4; nt++)
#pragma unroll
            for (int i = 0; i < 4; i++) acc[mt][nt][i] = 0.f;

    auto stage = [&](int c, int s) {
        int kc = c << 5;
        uint32_t ab = smb + (uint32_t)s * (A_ST * 4);
        const float* ag = A + (size_t)m0 * Kd + kc;
#pragma unroll
        for (int i = 0; i < 4; i++) {
            int q = tid + i * 256, r = q >> 3, ch = q & 7;
            CP_ASYNC16(ab + (uint32_t)(r * ASTR + ch * 4) * 4,
                       ag + (size_t)r * Kd + ch * 4);
        }
        uint32_t bb = smb + (uint32_t)(B_BASE + s * B_ST) * 4;
        const float* bg = B + (size_t)kc * N + n0;
#pragma unroll
        for (int i = 0; i < 4; i++) {
            int q = tid + i * 256, r = q >> 5, ch = q & 31;
            CP_ASYNC16(bb + (uint32_t)(r * BSTR + ch * 4) * 4,
                       bg + (size_t)r * N + ch * 4);
        }
    };

    stage(0, 0);
    CP_COMMIT();

    for (int c = 0; c < NC; c++) {
        if (c + 1 < NC) stage(c + 1, (c + 1) & 1);
        CP_COMMIT();
        CP_WAIT1();
        __syncthreads();
        const float* as = sm + (c & 1) * A_ST + wm * 64 * ASTR;
        const float* bs = sm + B_BASE + (c & 1) * B_ST + wn * 32;
#pragma unroll
        for (int ks = 0; ks < 4; ks++) {
            int k0 = ks * 8;
            uint32_t a[4][4], b[4][2];
#pragma unroll
            for (int mt = 0; mt < 4; mt++) {
                const float* ap = as + (mt * 16 + (lane >> 2)) * ASTR
                                     + k0 + (lane & 3);
                a[mt][0] = __float_as_uint(ap[0]);
                a[mt][1] = __float_as_uint(ap[8 * ASTR]);
                a[mt][2] = __float_as_uint(ap[4]);
                a[mt][3] = __float_as_uint(ap[8 * ASTR + 4]);
            }
#pragma unroll
            for (int nt = 0; nt < 4; nt++) {
                const float* bp = bs + (k0 + (lane & 3)) * BSTR
                                     + nt * 8 + (lane >> 2);
                b[nt][0] = __float_as_uint(bp[0]);
                b[nt][1] = __float_as_uint(bp[4 * BSTR]);
            }
#pragma unroll
            for (int mt = 0; mt < 4; mt++)
#pragma unroll
                for (int nt = 0; nt < 4; nt++)
                    asm volatile(
                        "mma.sync.aligned.m16n8k8.row.col.f32.tf32.tf32.f32 "
                        "{%0,%1,%2,%3}, {%4,%5,%6,%7}, {%8,%9}, {%0,%1,%2,%3};"
                        : "+f"(acc[mt][nt][0]), "+f"(acc[mt][nt][1]),
                          "+f"(acc[mt][nt][2]), "+f"(acc[mt][nt][3])
                        : "r"(a[mt][0]), "r"(a[mt][1]),
                          "r"(a[mt][2]), "r"(a[mt][3]),
                          "r"(b[nt][0]), "r"(b[nt][1]));
        }
        __syncthreads();
    }

    // epilogue: bias + act, float2 stores
#pragma unroll
    for (int mt = 0; mt < 4; mt++) {
        int r0 = m0 + wm * 64 + mt * 16 + (lane >> 2);
#pragma unroll
        for (int nt = 0; nt < 4; nt++) {
            int col = n0 + wn * 32 + nt * 8 + 2 * (lane & 3);
            float bb0 = __ldg(bias + col), bb1 = __ldg(bias + col + 1);
            float v0 = acc[mt][nt][0] + bb0, v1 = acc[mt][nt][1] + bb1;
            float v2 = acc[mt][nt][2] + bb0, v3 = acc[mt][nt][3] + bb1;
            if (RELU) {
                v0 = fmaxf(v0, 0.f); v1 = fmaxf(v1, 0.f);
                v2 = fmaxf(v2, 0.f); v3 = fmaxf(v3, 0.f);
            }
            float2 p0 = make_float2(v0, v1), p1 = make_float2(v2, v3);
            *(float2*)(C + (size_t)r0 * N + col) = p0;
            *(float2*)(C + (size_t)(r0 + 8) * N + col) = p1;
        }
    }
}

// ---------------- pi = log_softmax(uniqenc @ W_init + b_init) --------------
__global__ void __launch_bounds__(128) pi_kernel(
    const float* __restrict__ U, const float* __restrict__ W,
    const float* __restrict__ bias, float* __restrict__ pi) {
    __shared__ float u[TH2];
    __shared__ float red[4];
    int b = blockIdx.x, tid = threadIdx.x;
    for (int i = tid; i < TH2; i += 128) u[i] = U[b * TH2 + i];
    __syncthreads();
    float acc = bias[tid];
#pragma unroll 8
    for (int kk = 0; kk < TH2; kk++) acc += u[kk] * W[kk * KK + tid];
    float m = acc;
    for (int o = 16; o; o >>= 1) m = fmaxf(m, __shfl_xor_sync(~0u, m, o));
    if ((tid & 31) == 0) red[tid >> 5] = m;
    __syncthreads();
    m = fmaxf(fmaxf(red[0], red[1]), fmaxf(red[2], red[3]));
    __syncthreads();
    float e = __expf(acc - m);
    float s = e;
    for (int o = 16; o; o >>= 1) s += __shfl_xor_sync(~0u, s, o);
    if ((tid & 31) == 0) red[tid >> 5] = s;
    __syncthreads();
    s = red[0] + red[1] + red[2] + red[3];
    pi[b * KK + tid] = acc - m - __logf(s);
}

// ---------------- tscores = A_from @ A_to + diag(NEGINF) -------------------
__global__ void __launch_bounds__(128) tscores_kernel(
    const float* __restrict__ Af, const float* __restrict__ At,
    float* __restrict__ ts) {
    int k = blockIdx.x, j = threadIdx.x;
    float acc = (j == k) ? NEGINF : 0.f;
#pragma unroll
    for (int a = 0; a < ADIM; a++) acc += Af[k * ADIM + a] * At[a * KK + j];
    ts[k * KK + j] = acc;
}

// ---------------- fused trans-build + HSMM recurrence (1 block / batch) ----
#define SM_T    0
#define SM_CF   (SM_T + 128 * 129)
#define SM_CT   (SM_CF + 128 * 64)
#define SM_BUF  (SM_CT + 128 * 65)
#define SM_AV   (SM_BUF + 6 * 128)
#define SM_AP   (SM_AV + 128)
#define SM_PS   (SM_AP + 128)
#define SM_RED  (SM_PS + 256)
#define SM_TOTF (SM_RED + 8)
#define RECUR_SMEM (SM_TOTF * 4)

__global__ void __launch_bounds__(256, 1) recur_kernel(
    const float* __restrict__ pi, const float* __restrict__ cond,
    const float* __restrict__ ts, const float* __restrict__ obs,
    float* __restrict__ out) {
    extern __shared__ float smr[];
    float* T   = smr + SM_T;
    float* cf  = smr + SM_CF;
    float* ct  = smr + SM_CT;
    float* buf = smr + SM_BUF;
    float* av  = smr + SM_AV;
    float* ap  = smr + SM_AP;
    float* ps  = smr + SM_PS;
    float* red = smr + SM_RED;
    int tid = threadIdx.x, b = blockIdx.x;

    const float* crow = cond + (size_t)b * (KK * 2 * ADIM);
    for (int i = tid; i < 128 * 64; i += 256) {
        int k = i >> 6, a = i & 63;
        cf[k * 64 + a] = crow[k * 128 + a];
        ct[k * 65 + a] = crow[k * 128 + 64 + a];
    }
    __syncthreads();

    for (int mi = tid; mi < 2048; mi += 256) {
        int km = mi >> 5, jm = mi & 31;
        int k0 = km * 2;
        const float* f0 = cf + k0 * 64;
        const float* f1 = f0 + 64;
        float acc[2][4];
#pragma unroll
        for (int r = 0; r < 2; r++)
#pragma unroll
            for (int q = 0; q < 4; q++)
                acc[r][q] = ts[(k0 + r) * KK + jm + 32 * q];
#pragma unroll 16
        for (int a = 0; a < 64; a++) {
            float fa0 = f0[a], fa1 = f1[a];
#pragma unroll
            for (int q = 0; q < 4; q++) {
                float tv = ct[(jm + 32 * q) * 65 + a];
                acc[0][q] += fa0 * tv;
                acc[1][q] += fa1 * tv;
            }
        }
#pragma unroll
        for (int r = 0; r < 2; r++)
#pragma unroll
            for (int q = 0; q < 4; q++)
                T[(k0 + r) * 129 + jm + 32 * q] = acc[r][q];
    }
    __syncthreads();

    {
        int w = tid >> 5, lane = tid & 31;
        for (int r = 0; r < 16; r++) {
            int k = w * 16 + r;
            float v0 = T[k * 129 + lane];
            float v1 = T[k * 129 + lane + 32];
            float v2 = T[k * 129 + lane + 64];
            float v3 = T[k * 129 + lane + 96];
            float m = fmaxf(fmaxf(v0, v1), fmaxf(v2, v3));
            for (int o = 16; o; o >>= 1) m = fmaxf(m, __shfl_xor_sync(~0u, m, o));
            float e0 = __expf(v0 - m), e1 = __expf(v1 - m);
            float e2 = __expf(v2 - m), e3 = __expf(v3 - m);
            float s = e0 + e1 + e2 + e3;
            for (int o = 16; o; o >>= 1) s += __shfl_xor_sync(~0u, s, o);
            float inv = 1.f / s;
            T[k * 129 + lane]      = e0 * inv;
            T[k * 129 + lane + 32] = e1 * inv;
            T[k * 129 + lane + 64] = e2 * inv;
            T[k * 129 + lane + 96] = e3 * inv;
        }
    }

    for (int i = tid; i < LL * KK; i += 256) buf[i] = NEGINF;
    __syncthreads();
    if (tid < 128) buf[tid] = pi[b * KK + tid];
    __syncthreads();

    int head = 0;
    const float len_lp = -1.7917594692280550f;
    for (int t = 0; t < TT; t++) {
        if (tid < 128) {
            int j = tid;
            float s[LL];
            float m = -3.4e38f;
#pragma unroll
            for (int l = 0; l < LL; l++) {
                int tp = t - l;
                float o = (tp >= 0)
                    ? obs[(((size_t)l * TT + tp) * BSZ + b) * KK + j]
                    : NEGINF;
                int row = head + l; if (row >= LL) row -= LL;
                float v = buf[row * KK + j] + o;
                s[l] = v;
                m = fmaxf(m, v);
            }
            float se = 0.f;
#pragma unroll
            for (int l = 0; l < LL; l++) se += __expf(s[l] - m);
            float al = m + __logf(se) + len_lp;
            av[j] = al;
            float wm = al;
            for (int o = 16; o; o >>= 1) wm = fmaxf(wm, __shfl_xor_sync(~0u, wm, o));
            if ((tid & 31) == 0) red[tid >> 5] = wm;
        }
        __syncthreads();
        float am = fmaxf(fmaxf(red[0], red[1]), fmaxf(red[2], red[3]));
        if (tid < 128) ap[tid] = __expf(av[tid] - am);
        __syncthreads();
        {
            int j = tid & 127, hk = (tid >> 7) << 6;
            float acc = 0.f;
            const float* Tp = T + hk * 129 + j;
            const float* pp = ap + hk;
#pragma unroll 8
            for (int k = 0; k < 64; k++) acc += pp[k] * Tp[k * 129];
            ps[tid] = acc;
        }
        __syncthreads();
        int nh = (head == 0) ? (LL - 1) : (head - 1);
        if (tid < 128) {
            float ssum = ps[tid] + ps[128 + tid];
            float astar = am + __logf(ssum);
            if (!(astar > NEGINF)) astar = NEGINF;
            buf[nh * KK + tid] = astar;
        }
        head = nh;
        __syncthreads();
    }
    if (tid < 128) {
        float v = ap[tid];
        for (int o = 16; o; o >>= 1) v += __shfl_xor_sync(~0u, v, o);
        if ((tid & 31) == 0) red[4 + (tid >> 5)] = v;
    }
    __syncthreads();
    if (tid == 0) {
        float s = red[4] + red[5] + red[6] + red[7];
        float am = fmaxf(fmaxf(red[0], red[1]), fmaxf(red[2], red[3]));
        out[b] = am + __logf(s);
    }
}

// ---------------- launch ---------------------------------------------------
extern "C" void kernel_launch(void* const* d_in, const int* in_sizes, int n_in,
                              void* d_out, int out_size) {
    const float* uniqenc = (const float*)d_in[0];
    const float* obs_lps = (const float*)d_in[1];
    const float* W_init  = (const float*)d_in[2];
    const float* b_init  = (const float*)d_in[3];
    const float* A_from  = (const float*)d_in[4];
    const float* A_to    = (const float*)d_in[5];
    const float* W_c1    = (const float*)d_in[6];
    const float* b_c1    = (const float*)d_in[7];
    const float* W_c2    = (const float*)d_in[8];
    const float* b_c2    = (const float*)d_in[9];
    float* out = (float*)d_out;

    float *pi_p, *h_p, *cond_p, *ts_p;
    cudaGetSymbolAddress((void**)&pi_p, g_pi);
    cudaGetSymbolAddress((void**)&h_p, g_h);
    cudaGetSymbolAddress((void**)&cond_p, g_cond);
    cudaGetSymbolAddress((void**)&ts_p, g_ts);

    cudaFuncSetAttribute(recur_kernel,
                         cudaFuncAttributeMaxDynamicSharedMemorySize, RECUR_SMEM);
    cudaFuncSetAttribute(gemm_mma<true>,
                         cudaFuncAttributeMaxDynamicSharedMemorySize, GSMEM);
    cudaFuncSetAttribute(gemm_mma<false>,
                         cudaFuncAttributeMaxDynamicSharedMemorySize, GSMEM);

    pi_kernel<<<BSZ, 128>>>(uniqenc, W_init, b_init, pi_p);
    tscores_kernel<<<KK, 128>>>(A_from, A_to, ts_p);

    // h = relu(uniqenc @ W_c1 + b_c1): M=1024, N=8192, K=1024
    gemm_mma<true><<<dim3(8, 64), 256, GSMEM>>>(
        uniqenc, W_c1, b_c1, h_p, 1024, 8192, 1024);
    // cond = h @ W_c2 + b_c2: M=1024, N=16384, K=8192
    gemm_mma<false><<<dim3(8, 128), 256, GSMEM>>>(
        h_p, W_c2, b_c2, cond_p, 1024, 16384, 8192);

    recur_kernel<<<BSZ, 256, RECUR_SMEM>>>(pi_p, cond_p, ts_p, obs_lps, out);
}